// round 1
// baseline (speedup 1.0000x reference)
#include <cuda_runtime.h>
#include <math.h>

#define B_TOT   16384
#define NPART   16
#define NPAIR   120
#define HID     64
#define DLAT    5
#define TABN    8192
#define RMAX    16.0f

// ---------------------------------------------------------------------------
// Branchless exact-erf GELU (Abramowitz-Stegun 7.1.26, |err| <= 1.5e-7)
// gelu(x) = 0.5*x*(1 + erf(x/sqrt(2)))
// ---------------------------------------------------------------------------
__device__ __forceinline__ float gelu_f(float x) {
    float a = fabsf(x) * 0.70710678118654752f;
    float t = __fdividef(1.0f, fmaf(0.3275911f, a, 1.0f));
    float p = t * fmaf(t, fmaf(t, fmaf(t, fmaf(t, 1.061405429f, -1.453152027f),
                                        1.421413741f), -0.284496736f), 0.254829592f);
    float e = __expf(-a * a);
    float erfa = fmaf(-p, e, 1.0f);        // erf(|x|/sqrt2)
    erfa = copysignf(erfa, x);
    return 0.5f * x * (1.0f + erfa);
}

// psi table: per grid point, psi MLP output (5 floats) padded to 2 x float4
__device__ float4 g_tab[TABN * 2];

// ---------------------------------------------------------------------------
// Kernel 1: tabulate psi MLP over r grid
// ---------------------------------------------------------------------------
__global__ void build_psi_tab(const float* __restrict__ w0, const float* __restrict__ b0,
                              const float* __restrict__ w1, const float* __restrict__ b1,
                              const float* __restrict__ w2, const float* __restrict__ b2) {
    int i = blockIdx.x * blockDim.x + threadIdx.x;
    if (i >= TABN) return;
    float r = (RMAX / (float)(TABN - 1)) * (float)i;

    float f[6];
    f[0] = log1pf(r);
    f[1] = r / (1.0f + r);
    f[2] = expf(-r * r);
    f[3] = expf(-0.5f * r);
    f[4] = expf(-r);
    f[5] = expf(-2.0f * r);

    float h2[HID];
#pragma unroll
    for (int v = 0; v < HID; v++) h2[v] = b1[v];

    for (int u = 0; u < HID; u++) {
        const float* wr = w0 + u * 6;
        float pre = b0[u];
#pragma unroll
        for (int c = 0; c < 6; c++) pre = fmaf(wr[c], f[c], pre);
        float g = gelu_f(pre);
#pragma unroll
        for (int v = 0; v < HID; v++) h2[v] = fmaf(w1[v * HID + u], g, h2[v]);
    }

    float o[DLAT];
#pragma unroll
    for (int oo = 0; oo < DLAT; oo++) o[oo] = b2[oo];
#pragma unroll
    for (int v = 0; v < HID; v++) {
        float g = gelu_f(h2[v]);
#pragma unroll
        for (int oo = 0; oo < DLAT; oo++) o[oo] = fmaf(w2[oo * HID + v], g, o[oo]);
    }
    g_tab[2 * i]     = make_float4(o[0], o[1], o[2], o[3]);
    g_tab[2 * i + 1] = make_float4(o[4], 0.f, 0.f, 0.f);
}

// ---------------------------------------------------------------------------
// Kernel 2: main fused kernel. Warp handles 2 batches; half-warp per batch.
// Lane = particle for phi; half-warp strides pairs for psi lookup.
// ---------------------------------------------------------------------------
#define WARPS_PER_BLK 8

__global__ void __launch_bounds__(256)
jastrow_main(const float* __restrict__ x,
             const float* __restrict__ pw0, const float* __restrict__ pb0,
             const float* __restrict__ pw1, const float* __restrict__ pb1,
             const float* __restrict__ pw2, const float* __restrict__ pb2,
             const float* __restrict__ rw0, const float* __restrict__ rb0,
             const float* __restrict__ rw1, const float* __restrict__ rb1,
             float* __restrict__ out) {
    __shared__ __align__(16) float s_w1t[HID * HID];   // transposed phi W1: [in][out]
    __shared__ float s_w0[HID * 3];
    __shared__ float s_b0[HID], s_b1[HID];
    __shared__ float s_w2t[HID * DLAT];                // transposed phi W2: [in][out]
    __shared__ float s_b2[DLAT];
    __shared__ float s_rw0[HID * 10], s_rb0[HID], s_rw1[HID];
    __shared__ float s_rb1;
    __shared__ int   s_pi[NPAIR], s_pj[NPAIR];

    int t = threadIdx.x;
    for (int k = t; k < HID * 3; k += 256) s_w0[k] = pw0[k];
    for (int k = t; k < HID; k += 256) {
        s_b0[k] = pb0[k]; s_b1[k] = pb1[k]; s_rb0[k] = rb0[k]; s_rw1[k] = rw1[k];
    }
    for (int k = t; k < HID * HID; k += 256) {
        int o = k / HID, in = k % HID;
        s_w1t[in * HID + o] = pw1[k];
    }
    for (int k = t; k < HID * DLAT; k += 256) {
        int o = k / HID, v = k % HID;
        s_w2t[v * DLAT + o] = pw2[k];
    }
    for (int k = t; k < DLAT; k += 256) s_b2[k] = pb2[k];
    for (int k = t; k < HID * 10; k += 256) s_rw0[k] = rw0[k];
    if (t == 0) s_rb1 = rb1[0];
    if (t < NPAIR) {
        int p = t, i = 0, cnt = NPART - 1;
        while (p >= cnt) { p -= cnt; cnt--; i++; }
        s_pi[t] = i; s_pj[t] = i + 1 + p;
    }
    __syncthreads();

    int gw   = blockIdx.x * WARPS_PER_BLK + (t >> 5);
    int lane = t & 31;
    int lh   = lane & 15;
    int myb  = gw * 2 + (lane >> 4);
    const float2* xb = (const float2*)(x + (size_t)myb * (NPART * 2));

    // ---------------- Phase A: psi (table lookup) + cusp ----------------
    float ps0 = 0.f, ps1 = 0.f, ps2 = 0.f, ps3 = 0.f, ps4 = 0.f, cu = 0.f;
    const float INVH = (float)(TABN - 1) / RMAX;
#pragma unroll
    for (int k = 0; k < 8; k++) {
        int p = k * 16 + lh;
        if (p < NPAIR) {
            int i = s_pi[p], j = s_pj[p];
            float2 xi = xb[i], xj = xb[j];
            float dx = xi.x - xj.x, dy = xi.y - xj.y;
            float r = sqrtf(fmaf(dx, dx, fmaf(dy, dy, 1e-12f)));
            cu += r * __expf(-r);
            float tt = fminf(r * INVH, (float)(TABN - 2) + 0.999f);
            int   i0 = (int)tt;
            float fr = tt - (float)i0;
            float4 a = __ldg(&g_tab[2 * i0]);
            float4 b = __ldg(&g_tab[2 * i0 + 1]);
            float4 c = __ldg(&g_tab[2 * i0 + 2]);
            float4 d = __ldg(&g_tab[2 * i0 + 3]);
            ps0 += fmaf(fr, c.x - a.x, a.x);
            ps1 += fmaf(fr, c.y - a.y, a.y);
            ps2 += fmaf(fr, c.z - a.z, a.z);
            ps3 += fmaf(fr, c.w - a.w, a.w);
            ps4 += fmaf(fr, d.x - b.x, b.x);
        }
    }
#pragma unroll
    for (int d = 8; d >= 1; d >>= 1) {
        ps0 += __shfl_xor_sync(0xffffffffu, ps0, d, 16);
        ps1 += __shfl_xor_sync(0xffffffffu, ps1, d, 16);
        ps2 += __shfl_xor_sync(0xffffffffu, ps2, d, 16);
        ps3 += __shfl_xor_sync(0xffffffffu, ps3, d, 16);
        ps4 += __shfl_xor_sync(0xffffffffu, ps4, d, 16);
        cu  += __shfl_xor_sync(0xffffffffu, cu,  d, 16);
    }
    const float inv_np = 1.0f / (float)NPAIR;
    ps0 *= inv_np; ps1 *= inv_np; ps2 *= inv_np; ps3 *= inv_np; ps4 *= inv_np;

    // ---------------- Phase B: phi (exact fp32, lane = particle) ----------------
    float2 xm = xb[lh];
    float x0 = xm.x, x1 = xm.y;
    float r2 = fmaf(x0, x0, x1 * x1);

    float h2[HID];
#pragma unroll
    for (int v = 0; v < HID; v++) h2[v] = s_b1[v];

#pragma unroll 4
    for (int u = 0; u < HID; u++) {
        float pre = s_b0[u];
        pre = fmaf(s_w0[u * 3 + 0], x0, pre);
        pre = fmaf(s_w0[u * 3 + 1], x1, pre);
        pre = fmaf(s_w0[u * 3 + 2], r2, pre);
        float g = gelu_f(pre);
        const float4* wrow = (const float4*)(&s_w1t[u * HID]);
#pragma unroll
        for (int v4 = 0; v4 < HID / 4; v4++) {
            float4 w = wrow[v4];
            h2[4 * v4 + 0] = fmaf(w.x, g, h2[4 * v4 + 0]);
            h2[4 * v4 + 1] = fmaf(w.y, g, h2[4 * v4 + 1]);
            h2[4 * v4 + 2] = fmaf(w.z, g, h2[4 * v4 + 2]);
            h2[4 * v4 + 3] = fmaf(w.w, g, h2[4 * v4 + 3]);
        }
    }

    float o0 = 0.f, o1 = 0.f, o2 = 0.f, o3 = 0.f, o4 = 0.f;
#pragma unroll
    for (int v = 0; v < HID; v++) {
        float g = gelu_f(h2[v]);
        o0 = fmaf(s_w2t[v * DLAT + 0], g, o0);
        o1 = fmaf(s_w2t[v * DLAT + 1], g, o1);
        o2 = fmaf(s_w2t[v * DLAT + 2], g, o2);
        o3 = fmaf(s_w2t[v * DLAT + 3], g, o3);
        o4 = fmaf(s_w2t[v * DLAT + 4], g, o4);
    }
#pragma unroll
    for (int d = 8; d >= 1; d >>= 1) {
        o0 += __shfl_xor_sync(0xffffffffu, o0, d, 16);
        o1 += __shfl_xor_sync(0xffffffffu, o1, d, 16);
        o2 += __shfl_xor_sync(0xffffffffu, o2, d, 16);
        o3 += __shfl_xor_sync(0xffffffffu, o3, d, 16);
        o4 += __shfl_xor_sync(0xffffffffu, o4, d, 16);
    }
    const float inv_n = 1.0f / (float)NPART;
    o0 = fmaf(o0, inv_n, s_b2[0]);
    o1 = fmaf(o1, inv_n, s_b2[1]);
    o2 = fmaf(o2, inv_n, s_b2[2]);
    o3 = fmaf(o3, inv_n, s_b2[3]);
    o4 = fmaf(o4, inv_n, s_b2[4]);

    // ---------------- Phase C: rho readout ----------------
    float rin[10] = {o0, o1, o2, o3, o4, ps0, ps1, ps2, ps3, ps4};
    float facc = 0.f;
#pragma unroll
    for (int kk = 0; kk < 4; kk++) {
        int u = lh + kk * 16;
        const float* wr = &s_rw0[u * 10];
        float pre = s_rb0[u];
#pragma unroll
        for (int c = 0; c < 10; c++) pre = fmaf(wr[c], rin[c], pre);
        facc = fmaf(s_rw1[u], gelu_f(pre), facc);
    }
#pragma unroll
    for (int d = 8; d >= 1; d >>= 1)
        facc += __shfl_xor_sync(0xffffffffu, facc, d, 16);

    if (lh == 0) out[myb] = facc + s_rb1 + cu;
}

// ---------------------------------------------------------------------------
extern "C" void kernel_launch(void* const* d_in, const int* in_sizes, int n_in,
                              void* d_out, int out_size) {
    const float* x      = (const float*)d_in[0];
    const float* phi_w0 = (const float*)d_in[1];
    const float* phi_b0 = (const float*)d_in[2];
    const float* phi_w1 = (const float*)d_in[3];
    const float* phi_b1 = (const float*)d_in[4];
    const float* phi_w2 = (const float*)d_in[5];
    const float* phi_b2 = (const float*)d_in[6];
    const float* psi_w0 = (const float*)d_in[7];
    const float* psi_b0 = (const float*)d_in[8];
    const float* psi_w1 = (const float*)d_in[9];
    const float* psi_b1 = (const float*)d_in[10];
    const float* psi_w2 = (const float*)d_in[11];
    const float* psi_b2 = (const float*)d_in[12];
    const float* rho_w0 = (const float*)d_in[13];
    const float* rho_b0 = (const float*)d_in[14];
    const float* rho_w1 = (const float*)d_in[15];
    const float* rho_b1 = (const float*)d_in[16];

    build_psi_tab<<<TABN / 256, 256>>>(psi_w0, psi_b0, psi_w1, psi_b1, psi_w2, psi_b2);

    int nblk = B_TOT / (WARPS_PER_BLK * 2);   // 1024
    jastrow_main<<<nblk, 256>>>(x,
                                phi_w0, phi_b0, phi_w1, phi_b1, phi_w2, phi_b2,
                                rho_w0, rho_b0, rho_w1, rho_b1,
                                (float*)d_out);
}

// round 2
// speedup vs baseline: 2.1481x; 2.1481x over previous
#include <cuda_runtime.h>
#include <math.h>

#define B_TOT   16384
#define NPART   16
#define NPAIR   120
#define HID     64
#define DLAT    5
#define TABN    8192
#define RMAX    16.0f
#define GPHI    256
#define XR      6.5f

typedef unsigned long long ull;

// psi table: per r-grid point, psi MLP output (5 floats) padded to 2 x float4
__device__ float4 g_tab[TABN * 2];
// phi table: per (x0,x1) grid point, phi MLP output (5 floats, bias included) in 2 x float4
__device__ float4 g_phi[GPHI * GPHI * 2];

// ---------------------------------------------------------------------------
// Branchless exact-erf GELU (Abramowitz-Stegun 7.1.26, |err| <= 1.5e-7)
// ---------------------------------------------------------------------------
__device__ __forceinline__ float gelu_f(float x) {
    float a = fabsf(x) * 0.70710678118654752f;
    float t = __fdividef(1.0f, fmaf(0.3275911f, a, 1.0f));
    float p = t * fmaf(t, fmaf(t, fmaf(t, fmaf(t, 1.061405429f, -1.453152027f),
                                        1.421413741f), -0.284496736f), 0.254829592f);
    float e = __expf(-a * a);
    float erfa = fmaf(-p, e, 1.0f);
    erfa = copysignf(erfa, x);
    return 0.5f * x * (1.0f + erfa);
}

// ---- packed fp32x2 helpers (FFMA2 only reachable via PTX) ----
__device__ __forceinline__ ull pk2(float lo, float hi) {
    ull r; asm("mov.b64 %0, {%1, %2};" : "=l"(r) : "f"(lo), "f"(hi)); return r;
}
__device__ __forceinline__ void upk2(ull v, float& lo, float& hi) {
    asm("mov.b64 {%0, %1}, %2;" : "=f"(lo), "=f"(hi) : "l"(v));
}
__device__ __forceinline__ ull fma2(ull a, ull b, ull c) {
    ull d; asm("fma.rn.f32x2 %0, %1, %2, %3;" : "=l"(d) : "l"(a), "l"(b), "l"(c)); return d;
}

// ---------------------------------------------------------------------------
// Kernel 1: build BOTH tables.
//   blocks [0, GPHI)        : phi 2-D table, 256 points per block (1 pt/thread)
//   blocks [GPHI, GPHI+32)  : psi 1-D table, 256 points per block
// ---------------------------------------------------------------------------
__global__ void __launch_bounds__(256)
build_tabs(const float* __restrict__ pw0, const float* __restrict__ pb0,
           const float* __restrict__ pw1, const float* __restrict__ pb1,
           const float* __restrict__ pw2, const float* __restrict__ pb2,
           const float* __restrict__ qw0, const float* __restrict__ qb0,
           const float* __restrict__ qw1, const float* __restrict__ qb1,
           const float* __restrict__ qw2, const float* __restrict__ qb2) {
    __shared__ __align__(16) float s_w1t[HID * HID];   // [in][out]
    __shared__ float s_w0[HID * 3];
    __shared__ float s_b0[HID];
    __shared__ __align__(16) float s_b1[HID];
    __shared__ float s_w2t[HID * DLAT];                // [in][out]
    __shared__ float s_b2[DLAT];

    int t = threadIdx.x;

    if (blockIdx.x < GPHI) {
        // ---------------- phi 2-D table ----------------
        for (int k = t; k < HID * HID; k += 256) {
            int o = k / HID, in = k % HID;
            s_w1t[in * HID + o] = pw1[k];
        }
        for (int k = t; k < HID * 3; k += 256) s_w0[k] = pw0[k];
        for (int k = t; k < HID; k += 256) { s_b0[k] = pb0[k]; s_b1[k] = pb1[k]; }
        for (int k = t; k < HID * DLAT; k += 256) {
            int o = k / HID, v = k % HID;
            s_w2t[v * DLAT + o] = pw2[k];
        }
        for (int k = t; k < DLAT; k += 256) s_b2[k] = pb2[k];
        __syncthreads();

        int idx = blockIdx.x * 256 + t;            // 0..65535
        int ix = idx & (GPHI - 1), iy = idx >> 8;
        const float HX = 2.0f * XR / (float)(GPHI - 1);
        float x0 = -XR + HX * (float)ix;
        float x1 = -XR + HX * (float)iy;
        float r2 = fmaf(x0, x0, x1 * x1);

        ull h2p[HID / 2];
        const ull* b1p = (const ull*)s_b1;
#pragma unroll
        for (int v = 0; v < HID / 2; v++) h2p[v] = b1p[v];

#pragma unroll 4
        for (int u = 0; u < HID; u++) {
            float pre = s_b0[u];
            pre = fmaf(s_w0[u * 3 + 0], x0, pre);
            pre = fmaf(s_w0[u * 3 + 1], x1, pre);
            pre = fmaf(s_w0[u * 3 + 2], r2, pre);
            float g = gelu_f(pre);
            ull g2 = pk2(g, g);
            const ulonglong2* wrow = (const ulonglong2*)(&s_w1t[u * HID]);
#pragma unroll
            for (int k = 0; k < HID / 4; k++) {
                ulonglong2 q = wrow[k];
                h2p[2 * k]     = fma2(q.x, g2, h2p[2 * k]);
                h2p[2 * k + 1] = fma2(q.y, g2, h2p[2 * k + 1]);
            }
        }

        float o[DLAT];
#pragma unroll
        for (int oo = 0; oo < DLAT; oo++) o[oo] = s_b2[oo];
#pragma unroll
        for (int v2 = 0; v2 < HID / 2; v2++) {
            float a, b; upk2(h2p[v2], a, b);
            float ga = gelu_f(a), gb = gelu_f(b);
            const float* wa = &s_w2t[(2 * v2) * DLAT];
            const float* wb = &s_w2t[(2 * v2 + 1) * DLAT];
#pragma unroll
            for (int oo = 0; oo < DLAT; oo++)
                o[oo] = fmaf(wa[oo], ga, fmaf(wb[oo], gb, o[oo]));
        }
        g_phi[2 * idx]     = make_float4(o[0], o[1], o[2], o[3]);
        g_phi[2 * idx + 1] = make_float4(o[4], 0.f, 0.f, 0.f);
    } else {
        // ---------------- psi 1-D table ----------------
        int i = (blockIdx.x - GPHI) * 256 + t;     // 0..8191
        float r = (RMAX / (float)(TABN - 1)) * (float)i;

        float f[6];
        f[0] = log1pf(r);
        f[1] = r / (1.0f + r);
        f[2] = expf(-r * r);
        f[3] = expf(-0.5f * r);
        f[4] = expf(-r);
        f[5] = expf(-2.0f * r);

        float h2[HID];
#pragma unroll
        for (int v = 0; v < HID; v++) h2[v] = qb1[v];

        for (int u = 0; u < HID; u++) {
            const float* wr = qw0 + u * 6;
            float pre = qb0[u];
#pragma unroll
            for (int c = 0; c < 6; c++) pre = fmaf(wr[c], f[c], pre);
            float g = gelu_f(pre);
#pragma unroll
            for (int v = 0; v < HID; v++) h2[v] = fmaf(qw1[v * HID + u], g, h2[v]);
        }

        float o[DLAT];
#pragma unroll
        for (int oo = 0; oo < DLAT; oo++) o[oo] = qb2[oo];
#pragma unroll
        for (int v = 0; v < HID; v++) {
            float g = gelu_f(h2[v]);
#pragma unroll
            for (int oo = 0; oo < DLAT; oo++) o[oo] = fmaf(qw2[oo * HID + v], g, o[oo]);
        }
        g_tab[2 * i]     = make_float4(o[0], o[1], o[2], o[3]);
        g_tab[2 * i + 1] = make_float4(o[4], 0.f, 0.f, 0.f);
    }
}

// ---------------------------------------------------------------------------
// Kernel 2: main kernel — pure table lookups + cusp + rho readout.
// Warp = 2 batches; half-warp per batch; lane-within-half = particle / pair stride.
// ---------------------------------------------------------------------------
#define WARPS_PER_BLK 8

__global__ void __launch_bounds__(256)
jastrow_main(const float* __restrict__ x,
             const float* __restrict__ rw0, const float* __restrict__ rb0,
             const float* __restrict__ rw1, const float* __restrict__ rb1,
             float* __restrict__ out) {
    __shared__ float s_rw0[HID * 10], s_rb0[HID], s_rw1[HID];
    __shared__ float s_rb1;
    __shared__ int   s_pi[NPAIR], s_pj[NPAIR];

    int t = threadIdx.x;
    for (int k = t; k < HID; k += 256) { s_rb0[k] = rb0[k]; s_rw1[k] = rw1[k]; }
    for (int k = t; k < HID * 10; k += 256) s_rw0[k] = rw0[k];
    if (t == 0) s_rb1 = rb1[0];
    if (t < NPAIR) {
        int p = t, i = 0, cnt = NPART - 1;
        while (p >= cnt) { p -= cnt; cnt--; i++; }
        s_pi[t] = i; s_pj[t] = i + 1 + p;
    }
    __syncthreads();

    int gw   = blockIdx.x * WARPS_PER_BLK + (t >> 5);
    int lane = t & 31;
    int lh   = lane & 15;
    int myb  = gw * 2 + (lane >> 4);
    const float2* xb = (const float2*)(x + (size_t)myb * (NPART * 2));

    // ---------------- psi (1-D table) + cusp ----------------
    float ps0 = 0.f, ps1 = 0.f, ps2 = 0.f, ps3 = 0.f, ps4 = 0.f, cu = 0.f;
    const float INVH = (float)(TABN - 1) / RMAX;
#pragma unroll
    for (int k = 0; k < 8; k++) {
        int p = k * 16 + lh;
        if (p < NPAIR) {
            int i = s_pi[p], j = s_pj[p];
            float2 xi = xb[i], xj = xb[j];
            float dx = xi.x - xj.x, dy = xi.y - xj.y;
            float r = sqrtf(fmaf(dx, dx, fmaf(dy, dy, 1e-12f)));
            cu += r * __expf(-r);
            float tt = fminf(r * INVH, (float)(TABN - 2) + 0.999f);
            int   i0 = (int)tt;
            float fr = tt - (float)i0;
            float4 a = __ldg(&g_tab[2 * i0]);
            float4 b = __ldg(&g_tab[2 * i0 + 1]);
            float4 c = __ldg(&g_tab[2 * i0 + 2]);
            float4 d = __ldg(&g_tab[2 * i0 + 3]);
            ps0 += fmaf(fr, c.x - a.x, a.x);
            ps1 += fmaf(fr, c.y - a.y, a.y);
            ps2 += fmaf(fr, c.z - a.z, a.z);
            ps3 += fmaf(fr, c.w - a.w, a.w);
            ps4 += fmaf(fr, d.x - b.x, b.x);
        }
    }
#pragma unroll
    for (int d = 8; d >= 1; d >>= 1) {
        ps0 += __shfl_xor_sync(0xffffffffu, ps0, d, 16);
        ps1 += __shfl_xor_sync(0xffffffffu, ps1, d, 16);
        ps2 += __shfl_xor_sync(0xffffffffu, ps2, d, 16);
        ps3 += __shfl_xor_sync(0xffffffffu, ps3, d, 16);
        ps4 += __shfl_xor_sync(0xffffffffu, ps4, d, 16);
        cu  += __shfl_xor_sync(0xffffffffu, cu,  d, 16);
    }
    const float inv_np = 1.0f / (float)NPAIR;
    ps0 *= inv_np; ps1 *= inv_np; ps2 *= inv_np; ps3 *= inv_np; ps4 *= inv_np;

    // ---------------- phi (2-D bilinear table), lane = particle ----------------
    float2 xm = xb[lh];
    const float INVHX = (float)(GPHI - 1) / (2.0f * XR);
    float gxf = fminf(fmaxf((xm.x + XR) * INVHX, 0.0f), (float)(GPHI - 2) + 0.999f);
    float gyf = fminf(fmaxf((xm.y + XR) * INVHX, 0.0f), (float)(GPHI - 2) + 0.999f);
    int ix = (int)gxf, iy = (int)gyf;
    float fx = gxf - (float)ix, fy = gyf - (float)iy;

    const float4* p00 = &g_phi[((iy * GPHI + ix) << 1)];
    float4 a00 = __ldg(p00),            b00 = __ldg(p00 + 1);
    float4 a10 = __ldg(p00 + 2),        b10 = __ldg(p00 + 3);
    float4 a01 = __ldg(p00 + 2 * GPHI),     b01 = __ldg(p00 + 2 * GPHI + 1);
    float4 a11 = __ldg(p00 + 2 * GPHI + 2), b11 = __ldg(p00 + 2 * GPHI + 3);

    float w00 = (1.f - fx) * (1.f - fy);
    float w10 = fx * (1.f - fy);
    float w01 = (1.f - fx) * fy;
    float w11 = fx * fy;

    float o0 = w00 * a00.x + w10 * a10.x + w01 * a01.x + w11 * a11.x;
    float o1 = w00 * a00.y + w10 * a10.y + w01 * a01.y + w11 * a11.y;
    float o2 = w00 * a00.z + w10 * a10.z + w01 * a01.z + w11 * a11.z;
    float o3 = w00 * a00.w + w10 * a10.w + w01 * a01.w + w11 * a11.w;
    float o4 = w00 * b00.x + w10 * b10.x + w01 * b01.x + w11 * b11.x;

#pragma unroll
    for (int d = 8; d >= 1; d >>= 1) {
        o0 += __shfl_xor_sync(0xffffffffu, o0, d, 16);
        o1 += __shfl_xor_sync(0xffffffffu, o1, d, 16);
        o2 += __shfl_xor_sync(0xffffffffu, o2, d, 16);
        o3 += __shfl_xor_sync(0xffffffffu, o3, d, 16);
        o4 += __shfl_xor_sync(0xffffffffu, o4, d, 16);
    }
    const float inv_n = 1.0f / (float)NPART;
    o0 *= inv_n; o1 *= inv_n; o2 *= inv_n; o3 *= inv_n; o4 *= inv_n;

    // ---------------- rho readout ----------------
    float rin[10] = {o0, o1, o2, o3, o4, ps0, ps1, ps2, ps3, ps4};
    float facc = 0.f;
#pragma unroll
    for (int kk = 0; kk < 4; kk++) {
        int u = lh + kk * 16;
        const float* wr = &s_rw0[u * 10];
        float pre = s_rb0[u];
#pragma unroll
        for (int c = 0; c < 10; c++) pre = fmaf(wr[c], rin[c], pre);
        facc = fmaf(s_rw1[u], gelu_f(pre), facc);
    }
#pragma unroll
    for (int d = 8; d >= 1; d >>= 1)
        facc += __shfl_xor_sync(0xffffffffu, facc, d, 16);

    if (lh == 0) out[myb] = facc + s_rb1 + cu;
}

// ---------------------------------------------------------------------------
extern "C" void kernel_launch(void* const* d_in, const int* in_sizes, int n_in,
                              void* d_out, int out_size) {
    const float* x      = (const float*)d_in[0];
    const float* phi_w0 = (const float*)d_in[1];
    const float* phi_b0 = (const float*)d_in[2];
    const float* phi_w1 = (const float*)d_in[3];
    const float* phi_b1 = (const float*)d_in[4];
    const float* phi_w2 = (const float*)d_in[5];
    const float* phi_b2 = (const float*)d_in[6];
    const float* psi_w0 = (const float*)d_in[7];
    const float* psi_b0 = (const float*)d_in[8];
    const float* psi_w1 = (const float*)d_in[9];
    const float* psi_b1 = (const float*)d_in[10];
    const float* psi_w2 = (const float*)d_in[11];
    const float* psi_b2 = (const float*)d_in[12];
    const float* rho_w0 = (const float*)d_in[13];
    const float* rho_b0 = (const float*)d_in[14];
    const float* rho_w1 = (const float*)d_in[15];
    const float* rho_b1 = (const float*)d_in[16];

    build_tabs<<<GPHI + TABN / 256, 256>>>(phi_w0, phi_b0, phi_w1, phi_b1, phi_w2, phi_b2,
                                           psi_w0, psi_b0, psi_w1, psi_b1, psi_w2, psi_b2);

    int nblk = B_TOT / (WARPS_PER_BLK * 2);   // 1024
    jastrow_main<<<nblk, 256>>>(x, rho_w0, rho_b0, rho_w1, rho_b1, (float*)d_out);
}

// round 3
// speedup vs baseline: 2.9364x; 1.3670x over previous
#include <cuda_runtime.h>
#include <cuda_fp16.h>
#include <math.h>

#define B_TOT   16384
#define NPART   16
#define NPAIR   120
#define HID     64
#define DLAT    5
#define TABN    2048
#define RMAX    16.0f
#define GPHI    128
#define XR      6.5f

typedef unsigned long long ull;

// fp16-packed tables: one uint4 (8 halves) per grid point: {o0..o4, pad,pad,pad}
__device__ uint4 g_tab_h[TABN];
__device__ uint4 g_phi_h[GPHI * GPHI];

// ---------------------------------------------------------------------------
// Branchless exact-erf GELU (Abramowitz-Stegun 7.1.26, |err| <= 1.5e-7)
// ---------------------------------------------------------------------------
__device__ __forceinline__ float gelu_f(float x) {
    float a = fabsf(x) * 0.70710678118654752f;
    float t = __fdividef(1.0f, fmaf(0.3275911f, a, 1.0f));
    float p = t * fmaf(t, fmaf(t, fmaf(t, fmaf(t, 1.061405429f, -1.453152027f),
                                        1.421413741f), -0.284496736f), 0.254829592f);
    float e = __expf(-a * a);
    float erfa = fmaf(-p, e, 1.0f);
    erfa = copysignf(erfa, x);
    return 0.5f * x * (1.0f + erfa);
}

// ---- packed fp32x2 helpers (FFMA2 only reachable via PTX) ----
__device__ __forceinline__ ull pk2(float lo, float hi) {
    ull r; asm("mov.b64 %0, {%1, %2};" : "=l"(r) : "f"(lo), "f"(hi)); return r;
}
__device__ __forceinline__ void upk2(ull v, float& lo, float& hi) {
    asm("mov.b64 {%0, %1}, %2;" : "=f"(lo), "=f"(hi) : "l"(v));
}
__device__ __forceinline__ ull fma2(ull a, ull b, ull c) {
    ull d; asm("fma.rn.f32x2 %0, %1, %2, %3;" : "=l"(d) : "l"(a), "l"(b), "l"(c)); return d;
}

__device__ __forceinline__ uint4 pack5h(float o0, float o1, float o2, float o3, float o4) {
    uint4 e;
    __half2 p01 = __floats2half2_rn(o0, o1);
    __half2 p23 = __floats2half2_rn(o2, o3);
    __half2 p4x = __floats2half2_rn(o4, 0.0f);
    e.x = *reinterpret_cast<unsigned*>(&p01);
    e.y = *reinterpret_cast<unsigned*>(&p23);
    e.z = *reinterpret_cast<unsigned*>(&p4x);
    e.w = 0u;
    return e;
}

// ---------------------------------------------------------------------------
// Shared MLP evaluator body: h = gelu(L0) ; h2 = gelu(W1 h + b1) ; out = W2 h2 + b2
// pre-activation of layer0 per unit given in pre[], weights staged in smem.
// ---------------------------------------------------------------------------
struct SW {
    float w1t[HID * HID];   // [in][out], 16-byte aligned by placement first
    float w2t[HID * DLAT];  // [in][out]
    float b1[HID];
    float b2[DLAT];
};

__device__ __forceinline__ void mlp_tail(const SW* s, const float* preact,
                                         float o[DLAT]) {
    ull h2p[HID / 2];
    const ull* b1p = (const ull*)s->b1;
#pragma unroll
    for (int v = 0; v < HID / 2; v++) h2p[v] = b1p[v];

#pragma unroll 4
    for (int u = 0; u < HID; u++) {
        float g = gelu_f(preact[u]);
        ull g2 = pk2(g, g);
        const ulonglong2* wrow = (const ulonglong2*)(&s->w1t[u * HID]);
#pragma unroll
        for (int k = 0; k < HID / 4; k++) {
            ulonglong2 q = wrow[k];
            h2p[2 * k]     = fma2(q.x, g2, h2p[2 * k]);
            h2p[2 * k + 1] = fma2(q.y, g2, h2p[2 * k + 1]);
        }
    }
#pragma unroll
    for (int oo = 0; oo < DLAT; oo++) o[oo] = s->b2[oo];
#pragma unroll
    for (int v2 = 0; v2 < HID / 2; v2++) {
        float a, b; upk2(h2p[v2], a, b);
        float ga = gelu_f(a), gb = gelu_f(b);
        const float* wa = &s->w2t[(2 * v2) * DLAT];
        const float* wb = &s->w2t[(2 * v2 + 1) * DLAT];
#pragma unroll
        for (int oo = 0; oo < DLAT; oo++)
            o[oo] = fmaf(wa[oo], ga, fmaf(wb[oo], gb, o[oo]));
    }
}

__device__ __forceinline__ void stage_tail(SW* s, int t, int nt,
                                           const float* w1, const float* b1,
                                           const float* w2, const float* b2) {
    for (int k = t; k < HID * HID; k += nt) {
        int o = k / HID, in = k % HID;
        s->w1t[in * HID + o] = w1[k];
    }
    for (int k = t; k < HID; k += nt) s->b1[k] = b1[k];
    for (int k = t; k < HID * DLAT; k += nt) {
        int o = k / HID, v = k % HID;
        s->w2t[v * DLAT + o] = w2[k];
    }
    for (int k = t; k < DLAT; k += nt) s->b2[k] = b2[k];
}

// ---------------------------------------------------------------------------
// Kernel 1a: phi 2-D table (GPHI x GPHI), one point per thread.
// ---------------------------------------------------------------------------
__global__ void __launch_bounds__(256)
build_phi(const float* __restrict__ w0, const float* __restrict__ b0,
          const float* __restrict__ w1, const float* __restrict__ b1,
          const float* __restrict__ w2, const float* __restrict__ b2) {
    __shared__ __align__(16) SW s;
    __shared__ float s_w0[HID * 3], s_b0[HID];
    int t = threadIdx.x;
    stage_tail(&s, t, 256, w1, b1, w2, b2);
    for (int k = t; k < HID * 3; k += 256) s_w0[k] = w0[k];
    for (int k = t; k < HID; k += 256) s_b0[k] = b0[k];
    __syncthreads();

    int idx = blockIdx.x * 256 + t;
    int ix = idx & (GPHI - 1), iy = idx >> 7;   // GPHI=128
    const float HX = 2.0f * XR / (float)(GPHI - 1);
    float x0 = -XR + HX * (float)ix;
    float x1 = -XR + HX * (float)iy;
    float r2 = fmaf(x0, x0, x1 * x1);

    float pre[HID];
#pragma unroll 8
    for (int u = 0; u < HID; u++) {
        float p = s_b0[u];
        p = fmaf(s_w0[u * 3 + 0], x0, p);
        p = fmaf(s_w0[u * 3 + 1], x1, p);
        pre[u] = fmaf(s_w0[u * 3 + 2], r2, p);
    }
    float o[DLAT];
    mlp_tail(&s, pre, o);
    g_phi_h[idx] = pack5h(o[0], o[1], o[2], o[3], o[4]);
}

// ---------------------------------------------------------------------------
// Kernel 1b: psi 1-D table (TABN), one point per thread.
// ---------------------------------------------------------------------------
__global__ void __launch_bounds__(256)
build_psi(const float* __restrict__ w0, const float* __restrict__ b0,
          const float* __restrict__ w1, const float* __restrict__ b1,
          const float* __restrict__ w2, const float* __restrict__ b2) {
    __shared__ __align__(16) SW s;
    __shared__ float s_w0[HID * 6], s_b0[HID];
    int t = threadIdx.x;
    stage_tail(&s, t, 256, w1, b1, w2, b2);
    for (int k = t; k < HID * 6; k += 256) s_w0[k] = w0[k];
    for (int k = t; k < HID; k += 256) s_b0[k] = b0[k];
    __syncthreads();

    int i = blockIdx.x * 256 + t;
    float r = (RMAX / (float)(TABN - 1)) * (float)i;

    float f[6];
    f[0] = log1pf(r);
    f[1] = r / (1.0f + r);
    f[2] = expf(-r * r);
    f[3] = expf(-0.5f * r);
    f[4] = expf(-r);
    f[5] = expf(-2.0f * r);

    float pre[HID];
#pragma unroll 8
    for (int u = 0; u < HID; u++) {
        const float* wr = &s_w0[u * 6];
        float p = s_b0[u];
#pragma unroll
        for (int c = 0; c < 6; c++) p = fmaf(wr[c], f[c], p);
        pre[u] = p;
    }
    float o[DLAT];
    mlp_tail(&s, pre, o);
    g_tab_h[i] = pack5h(o[0], o[1], o[2], o[3], o[4]);
}

// ---------------------------------------------------------------------------
// Kernel 2: main kernel. psi table lives in smem. Warp = 2 batches,
// half-warp per batch, lane-within-half = particle / pair stride.
// ---------------------------------------------------------------------------
#define MAIN_THREADS 512

__global__ void __launch_bounds__(MAIN_THREADS)
jastrow_main(const float* __restrict__ x,
             const float* __restrict__ rw0, const float* __restrict__ rb0,
             const float* __restrict__ rw1, const float* __restrict__ rb1,
             float* __restrict__ out) {
    __shared__ __align__(16) uint4 s_tab[TABN];        // 32 KB psi table
    __shared__ float s_rw0[HID * 10], s_rb0[HID], s_rw1[HID];
    __shared__ float s_rb1;
    __shared__ int   s_pi[NPAIR], s_pj[NPAIR];

    int t = threadIdx.x;
    for (int k = t; k < TABN; k += MAIN_THREADS) s_tab[k] = g_tab_h[k];
    for (int k = t; k < HID; k += MAIN_THREADS) { s_rb0[k] = rb0[k]; s_rw1[k] = rw1[k]; }
    for (int k = t; k < HID * 10; k += MAIN_THREADS) s_rw0[k] = rw0[k];
    if (t == 0) s_rb1 = rb1[0];
    if (t < NPAIR) {
        int p = t, i = 0, cnt = NPART - 1;
        while (p >= cnt) { p -= cnt; cnt--; i++; }
        s_pi[t] = i; s_pj[t] = i + 1 + p;
    }
    __syncthreads();

    int gw   = blockIdx.x * (MAIN_THREADS / 32) + (t >> 5);
    int lane = t & 31;
    int lh   = lane & 15;
    int myb  = gw * 2 + (lane >> 4);
    const float2* xb = (const float2*)(x + (size_t)myb * (NPART * 2));

    // ---------------- psi (smem fp16 table) + cusp ----------------
    float ps0 = 0.f, ps1 = 0.f, ps2 = 0.f, ps3 = 0.f, ps4 = 0.f, cu = 0.f;
    const float INVH = (float)(TABN - 1) / RMAX;
#pragma unroll
    for (int k = 0; k < 8; k++) {
        int p = k * 16 + lh;
        if (p < NPAIR) {
            int i = s_pi[p], j = s_pj[p];
            float2 xi = __ldg(&xb[i]), xj = __ldg(&xb[j]);
            float dx = xi.x - xj.x, dy = xi.y - xj.y;
            float r = sqrtf(fmaf(dx, dx, fmaf(dy, dy, 1e-12f)));
            cu += r * __expf(-r);
            float tt = fminf(r * INVH, (float)(TABN - 2) + 0.999f);
            int   i0 = (int)tt;
            float fr = tt - (float)i0;
            uint4 ea = s_tab[i0];
            uint4 eb = s_tab[i0 + 1];
            float2 a01 = __half22float2(*reinterpret_cast<__half2*>(&ea.x));
            float2 a23 = __half22float2(*reinterpret_cast<__half2*>(&ea.y));
            float2 a4_ = __half22float2(*reinterpret_cast<__half2*>(&ea.z));
            float2 b01 = __half22float2(*reinterpret_cast<__half2*>(&eb.x));
            float2 b23 = __half22float2(*reinterpret_cast<__half2*>(&eb.y));
            float2 b4_ = __half22float2(*reinterpret_cast<__half2*>(&eb.z));
            ps0 += fmaf(fr, b01.x - a01.x, a01.x);
            ps1 += fmaf(fr, b01.y - a01.y, a01.y);
            ps2 += fmaf(fr, b23.x - a23.x, a23.x);
            ps3 += fmaf(fr, b23.y - a23.y, a23.y);
            ps4 += fmaf(fr, b4_.x - a4_.x, a4_.x);
        }
    }
#pragma unroll
    for (int d = 8; d >= 1; d >>= 1) {
        ps0 += __shfl_xor_sync(0xffffffffu, ps0, d, 16);
        ps1 += __shfl_xor_sync(0xffffffffu, ps1, d, 16);
        ps2 += __shfl_xor_sync(0xffffffffu, ps2, d, 16);
        ps3 += __shfl_xor_sync(0xffffffffu, ps3, d, 16);
        ps4 += __shfl_xor_sync(0xffffffffu, ps4, d, 16);
        cu  += __shfl_xor_sync(0xffffffffu, cu,  d, 16);
    }
    const float inv_np = 1.0f / (float)NPAIR;
    ps0 *= inv_np; ps1 *= inv_np; ps2 *= inv_np; ps3 *= inv_np; ps4 *= inv_np;

    // ---------------- phi (fp16 2-D bilinear table), lane = particle ----------------
    float2 xm = __ldg(&xb[lh]);
    const float INVHX = (float)(GPHI - 1) / (2.0f * XR);
    float gxf = fminf(fmaxf((xm.x + XR) * INVHX, 0.0f), (float)(GPHI - 2) + 0.999f);
    float gyf = fminf(fmaxf((xm.y + XR) * INVHX, 0.0f), (float)(GPHI - 2) + 0.999f);
    int ix = (int)gxf, iy = (int)gyf;
    float fx = gxf - (float)ix, fy = gyf - (float)iy;

    const uint4* p00 = &g_phi_h[iy * GPHI + ix];
    uint4 e00 = __ldg(p00);
    uint4 e10 = __ldg(p00 + 1);
    uint4 e01 = __ldg(p00 + GPHI);
    uint4 e11 = __ldg(p00 + GPHI + 1);

    float w00 = (1.f - fx) * (1.f - fy);
    float w10 = fx * (1.f - fy);
    float w01 = (1.f - fx) * fy;
    float w11 = fx * fy;

    float2 c00a = __half22float2(*reinterpret_cast<__half2*>(&e00.x));
    float2 c00b = __half22float2(*reinterpret_cast<__half2*>(&e00.y));
    float2 c00c = __half22float2(*reinterpret_cast<__half2*>(&e00.z));
    float2 c10a = __half22float2(*reinterpret_cast<__half2*>(&e10.x));
    float2 c10b = __half22float2(*reinterpret_cast<__half2*>(&e10.y));
    float2 c10c = __half22float2(*reinterpret_cast<__half2*>(&e10.z));
    float2 c01a = __half22float2(*reinterpret_cast<__half2*>(&e01.x));
    float2 c01b = __half22float2(*reinterpret_cast<__half2*>(&e01.y));
    float2 c01c = __half22float2(*reinterpret_cast<__half2*>(&e01.z));
    float2 c11a = __half22float2(*reinterpret_cast<__half2*>(&e11.x));
    float2 c11b = __half22float2(*reinterpret_cast<__half2*>(&e11.y));
    float2 c11c = __half22float2(*reinterpret_cast<__half2*>(&e11.z));

    float o0 = w00 * c00a.x + w10 * c10a.x + w01 * c01a.x + w11 * c11a.x;
    float o1 = w00 * c00a.y + w10 * c10a.y + w01 * c01a.y + w11 * c11a.y;
    float o2 = w00 * c00b.x + w10 * c10b.x + w01 * c01b.x + w11 * c11b.x;
    float o3 = w00 * c00b.y + w10 * c10b.y + w01 * c01b.y + w11 * c11b.y;
    float o4 = w00 * c00c.x + w10 * c10c.x + w01 * c01c.x + w11 * c11c.x;

#pragma unroll
    for (int d = 8; d >= 1; d >>= 1) {
        o0 += __shfl_xor_sync(0xffffffffu, o0, d, 16);
        o1 += __shfl_xor_sync(0xffffffffu, o1, d, 16);
        o2 += __shfl_xor_sync(0xffffffffu, o2, d, 16);
        o3 += __shfl_xor_sync(0xffffffffu, o3, d, 16);
        o4 += __shfl_xor_sync(0xffffffffu, o4, d, 16);
    }
    const float inv_n = 1.0f / (float)NPART;
    o0 *= inv_n; o1 *= inv_n; o2 *= inv_n; o3 *= inv_n; o4 *= inv_n;

    // ---------------- rho readout ----------------
    float rin[10] = {o0, o1, o2, o3, o4, ps0, ps1, ps2, ps3, ps4};
    float facc = 0.f;
#pragma unroll
    for (int kk = 0; kk < 4; kk++) {
        int u = lh + kk * 16;
        const float* wr = &s_rw0[u * 10];
        float pre = s_rb0[u];
#pragma unroll
        for (int c = 0; c < 10; c++) pre = fmaf(wr[c], rin[c], pre);
        facc = fmaf(s_rw1[u], gelu_f(pre), facc);
    }
#pragma unroll
    for (int d = 8; d >= 1; d >>= 1)
        facc += __shfl_xor_sync(0xffffffffu, facc, d, 16);

    if (lh == 0) out[myb] = facc + s_rb1 + cu;
}

// ---------------------------------------------------------------------------
extern "C" void kernel_launch(void* const* d_in, const int* in_sizes, int n_in,
                              void* d_out, int out_size) {
    const float* x      = (const float*)d_in[0];
    const float* phi_w0 = (const float*)d_in[1];
    const float* phi_b0 = (const float*)d_in[2];
    const float* phi_w1 = (const float*)d_in[3];
    const float* phi_b1 = (const float*)d_in[4];
    const float* phi_w2 = (const float*)d_in[5];
    const float* phi_b2 = (const float*)d_in[6];
    const float* psi_w0 = (const float*)d_in[7];
    const float* psi_b0 = (const float*)d_in[8];
    const float* psi_w1 = (const float*)d_in[9];
    const float* psi_b1 = (const float*)d_in[10];
    const float* psi_w2 = (const float*)d_in[11];
    const float* psi_b2 = (const float*)d_in[12];
    const float* rho_w0 = (const float*)d_in[13];
    const float* rho_b0 = (const float*)d_in[14];
    const float* rho_w1 = (const float*)d_in[15];
    const float* rho_b1 = (const float*)d_in[16];

    build_phi<<<GPHI * GPHI / 256, 256>>>(phi_w0, phi_b0, phi_w1, phi_b1, phi_w2, phi_b2);
    build_psi<<<TABN / 256, 256>>>(psi_w0, psi_b0, psi_w1, psi_b1, psi_w2, psi_b2);

    int nblk = B_TOT / (MAIN_THREADS / 32 * 2);   // 512
    jastrow_main<<<nblk, MAIN_THREADS>>>(x, rho_w0, rho_b0, rho_w1, rho_b1, (float*)d_out);
}